// round 3
// baseline (speedup 1.0000x reference)
#include <cuda_runtime.h>
#include <cuda_bf16.h>
#include <math.h>
#include <stdint.h>

#define T_ 2048
#define H_ 2048
#define NH_ 16
#define NKV_ 4
#define DH_ 128
#define E_ 16
#define TOPK_ 2
#define I_ 1024
#define EPS_ 1e-6f

// ---------------- fp32 scratch ----------------
__device__ float g_x[(size_t)T_ * H_];
__device__ float g_res[(size_t)T_ * H_];
__device__ float g_xn[(size_t)T_ * H_];
__device__ float g_q[(size_t)T_ * NH_ * DH_];
__device__ float g_k[(size_t)T_ * NKV_ * DH_];
__device__ float g_v[(size_t)T_ * NKV_ * DH_];
__device__ float g_gbuf[(size_t)T_ * TOPK_ * I_];
__device__ float g_ubuf[(size_t)T_ * TOPK_ * I_];
__device__ float g_downbuf[(size_t)T_ * TOPK_ * H_];
__device__ int   g_top_idx[T_ * TOPK_];
__device__ float g_top_w[T_ * TOPK_];
__device__ int   g_counts[E_];
__device__ int   g_counts2[E_];
__device__ int   g_offs[E_ + 1];
__device__ int   g_tok_of_slot[T_ * TOPK_];
__device__ float g_gate_of_slot[T_ * TOPK_];
__device__ int   g_slot_of_tok[T_ * TOPK_];

// ---------------- bf16 split (hi/lo) buffers ----------------
// weights, converted once per launch
#define WOFF_FC 0LL
#define WOFF_Q  8388608LL
#define WOFF_K  12582912LL
#define WOFF_V  13631488LL
#define WOFF_O  14680064LL
#define WOFF_G  18874368LL
#define WOFF_U  52428800LL
#define WOFF_D  85983232LL
#define WTOT    119537664LL
__device__ __nv_bfloat16 wb_h[WTOT];
__device__ __nv_bfloat16 wb_l[WTOT];

// activations
#define AOFF_CAT  0LL                       // T*2H = 8388608
#define AOFF_XN   8388608LL                 // T*H  = 4194304
#define AOFF_ATTN 12582912LL                // T*NH*DH = 4194304
#define AOFF_ACT  16777216LL                // T*2*I = 4194304
#define ATOT      20971520LL
__device__ __nv_bfloat16 ab_h[ATOT];
__device__ __nv_bfloat16 ab_l[ATOT];

// ---------------- helpers ----------------
__device__ __forceinline__ float block_reduce_sum(float v) {
    __shared__ float sb[33];
    int tid = threadIdx.x;
#pragma unroll
    for (int o = 16; o > 0; o >>= 1) v += __shfl_xor_sync(0xffffffffu, v, o);
    if ((tid & 31) == 0) sb[tid >> 5] = v;
    __syncthreads();
    if (tid == 0) {
        float s = 0.f;
        int nw = (blockDim.x + 31) >> 5;
        for (int i = 0; i < nw; i++) s += sb[i];
        sb[32] = s;
    }
    __syncthreads();
    return sb[32];
}

__device__ __forceinline__ void split1(float x, __nv_bfloat16* hp, __nv_bfloat16* lp) {
    __nv_bfloat16 hx = __float2bfloat16_rn(x);
    *hp = hx;
    *lp = __float2bfloat16_rn(x - __bfloat162float(hx));
}

__device__ __forceinline__ uint32_t cvta_s(const void* p) {
    return (uint32_t)__cvta_generic_to_shared(p);
}

__device__ __forceinline__ void ldm_x4(uint32_t* r, uint32_t a) {
    asm volatile("ldmatrix.sync.aligned.m8n8.x4.shared.b16 {%0,%1,%2,%3}, [%4];"
                 : "=r"(r[0]), "=r"(r[1]), "=r"(r[2]), "=r"(r[3]) : "r"(a));
}
__device__ __forceinline__ void ldm_x2t(uint32_t* r, uint32_t a) {
    asm volatile("ldmatrix.sync.aligned.m8n8.x2.trans.shared.b16 {%0,%1}, [%2];"
                 : "=r"(r[0]), "=r"(r[1]) : "r"(a));
}
__device__ __forceinline__ void mma_bf16(float* d, const uint32_t* a, const uint32_t* b) {
    asm volatile("mma.sync.aligned.m16n8k16.row.col.f32.bf16.bf16.f32 "
                 "{%0,%1,%2,%3}, {%4,%5,%6,%7}, {%8,%9}, {%0,%1,%2,%3};"
                 : "+f"(d[0]), "+f"(d[1]), "+f"(d[2]), "+f"(d[3])
                 : "r"(a[0]), "r"(a[1]), "r"(a[2]), "r"(a[3]), "r"(b[0]), "r"(b[1]));
}

// ---------------- weight split conversion ----------------
__global__ void cvt_split(const float* __restrict__ x, __nv_bfloat16* __restrict__ h,
                          __nv_bfloat16* __restrict__ l, long long n) {
    long long i = ((long long)blockIdx.x * blockDim.x + threadIdx.x) * 4;
    if (i >= n) return;
    float4 v = *reinterpret_cast<const float4*>(x + i);
    __nv_bfloat16 h0 = __float2bfloat16_rn(v.x), h1 = __float2bfloat16_rn(v.y);
    __nv_bfloat16 h2 = __float2bfloat16_rn(v.z), h3 = __float2bfloat16_rn(v.w);
    __nv_bfloat162 hh0; hh0.x = h0; hh0.y = h1;
    __nv_bfloat162 hh1; hh1.x = h2; hh1.y = h3;
    *reinterpret_cast<__nv_bfloat162*>(h + i) = hh0;
    *reinterpret_cast<__nv_bfloat162*>(h + i + 2) = hh1;
    __nv_bfloat162 ll0, ll1;
    ll0.x = __float2bfloat16_rn(v.x - __bfloat162float(h0));
    ll0.y = __float2bfloat16_rn(v.y - __bfloat162float(h1));
    ll1.x = __float2bfloat16_rn(v.z - __bfloat162float(h2));
    ll1.y = __float2bfloat16_rn(v.w - __bfloat162float(h3));
    *reinterpret_cast<__nv_bfloat162*>(l + i) = ll0;
    *reinterpret_cast<__nv_bfloat162*>(l + i + 2) = ll1;
}

// ---------------- split-bf16 tensor-core GEMM ----------------
// C[M,N] = gather(A)[M,K] * B[K,N], A/B given as bf16 hi/lo pairs.
// 128x128x32 tile, 8 warps (2m x 4n), warp tile 64x32, mma m16n8k16, 3-pass split.
#define APITCH 40
#define BPITCH 136
#define GSMEM_BYTES ((2 * 128 * APITCH + 2 * 32 * BPITCH) * 2 * 2)

__global__ __launch_bounds__(256, 1)
void gemm_mma(const __nv_bfloat16* __restrict__ Ah_g, const __nv_bfloat16* __restrict__ Al_g,
              const __nv_bfloat16* __restrict__ Bh_g, const __nv_bfloat16* __restrict__ Bl_g,
              float* __restrict__ C,
              int M, int N, int Kd, int lda, int ldb, int ldc,
              const int* __restrict__ rowmap,
              const float* __restrict__ addsrc, float* __restrict__ Cdup,
              const int* __restrict__ segoff, long long strideB,
              const float* __restrict__ rowscale) {
    int row0 = 0, rowEnd = M;
    long long boff = 0;
    if (segoff) {
        int e = blockIdx.z;
        row0 = segoff[e];
        rowEnd = segoff[e + 1];
        boff = (long long)e * strideB;
    }
    int rbase = row0 + blockIdx.y * 128;
    if (rbase >= rowEnd) return;
    int cbase = blockIdx.x * 128;

    extern __shared__ __nv_bfloat16 sm[];
    __nv_bfloat16* As_h = sm;
    __nv_bfloat16* As_l = As_h + 2 * 128 * APITCH;
    __nv_bfloat16* Bs_h = As_l + 2 * 128 * APITCH;
    __nv_bfloat16* Bs_l = Bs_h + 2 * 32 * BPITCH;

    int tid = threadIdx.x, lane = tid & 31, wid = tid >> 5;
    int wm = wid & 1, wn = wid >> 1;

    // gmem staging maps
    int ar = tid & 127;            // A row in tile
    int ak = (tid >> 7) * 16;      // A k-offset (0/16)
    int grow = rbase + ar;
    const __nv_bfloat16 *Arh = nullptr, *Arl = nullptr;
    if (grow < rowEnd) {
        int m = rowmap ? rowmap[grow] : grow;
        Arh = Ah_g + (long long)m * lda;
        Arl = Al_g + (long long)m * lda;
    }
    int br = tid >> 3;             // B k-row in tile (0..31)
    int bc = (tid & 7) * 16;       // B col offset
    const __nv_bfloat16* Bh0 = Bh_g + boff + (long long)br * ldb + cbase + bc;
    const __nv_bfloat16* Bl0 = Bl_g + boff + (long long)br * ldb + cbase + bc;

    float acc[4][4][4];
#pragma unroll
    for (int a = 0; a < 4; a++)
#pragma unroll
        for (int b = 0; b < 4; b++)
#pragma unroll
            for (int c = 0; c < 4; c++) acc[a][b][c] = 0.f;

    uint4 rAh0, rAh1, rAl0, rAl1, rBh0, rBh1, rBl0, rBl1;
    const uint4 Z4 = make_uint4(0, 0, 0, 0);

#define LOAD_G(K0)                                                                   \
    do {                                                                             \
        if (Arh) {                                                                   \
            rAh0 = *(const uint4*)(Arh + (K0) + ak);                                 \
            rAh1 = *(const uint4*)(Arh + (K0) + ak + 8);                             \
            rAl0 = *(const uint4*)(Arl + (K0) + ak);                                 \
            rAl1 = *(const uint4*)(Arl + (K0) + ak + 8);                             \
        } else { rAh0 = rAh1 = rAl0 = rAl1 = Z4; }                                   \
        rBh0 = *(const uint4*)(Bh0 + (long long)(K0) * ldb);                         \
        rBh1 = *(const uint4*)(Bh0 + (long long)(K0) * ldb + 8);                     \
        rBl0 = *(const uint4*)(Bl0 + (long long)(K0) * ldb);                         \
        rBl1 = *(const uint4*)(Bl0 + (long long)(K0) * ldb + 8);                     \
    } while (0)

#define STORE_S(BUF)                                                                 \
    do {                                                                             \
        __nv_bfloat16* pAh = As_h + (BUF) * 128 * APITCH + ar * APITCH + ak;         \
        __nv_bfloat16* pAl = As_l + (BUF) * 128 * APITCH + ar * APITCH + ak;         \
        *(uint4*)pAh = rAh0; *(uint4*)(pAh + 8) = rAh1;                              \
        *(uint4*)pAl = rAl0; *(uint4*)(pAl + 8) = rAl1;                              \
        __nv_bfloat16* pBh = Bs_h + (BUF) * 32 * BPITCH + br * BPITCH + bc;          \
        __nv_bfloat16* pBl = Bs_l + (BUF) * 32 * BPITCH + br * BPITCH + bc;          \
        *(uint4*)pBh = rBh0; *(uint4*)(pBh + 8) = rBh1;                              \
        *(uint4*)pBl = rBl0; *(uint4*)(pBl + 8) = rBl1;                              \
    } while (0)

    int nk = Kd >> 5;
    LOAD_G(0);
    STORE_S(0);
    __syncthreads();

    for (int kt = 0; kt < nk; kt++) {
        int cur = kt & 1;
        bool have_next = (kt + 1 < nk);
        if (have_next) LOAD_G((kt + 1) * 32);

        const __nv_bfloat16* Abh = As_h + cur * 128 * APITCH;
        const __nv_bfloat16* Abl = As_l + cur * 128 * APITCH;
        const __nv_bfloat16* Bbh = Bs_h + cur * 32 * BPITCH;
        const __nv_bfloat16* Bbl = Bs_l + cur * 32 * BPITCH;
#pragma unroll
        for (int ks = 0; ks < 2; ks++) {
            uint32_t ah[4][4], al[4][4], bh[4][2], bl[4][2];
            int arow = wm * 64 + (lane & 15);
            int acol = ks * 16 + (lane >> 4) * 8;
#pragma unroll
            for (int mt = 0; mt < 4; mt++) {
                ldm_x4(ah[mt], cvta_s(Abh + (arow + mt * 16) * APITCH + acol));
                ldm_x4(al[mt], cvta_s(Abl + (arow + mt * 16) * APITCH + acol));
            }
            int brow = ks * 16 + (lane & 15);
#pragma unroll
            for (int nt = 0; nt < 4; nt++) {
                ldm_x2t(bh[nt], cvta_s(Bbh + brow * BPITCH + wn * 32 + nt * 8));
                ldm_x2t(bl[nt], cvta_s(Bbl + brow * BPITCH + wn * 32 + nt * 8));
            }
#pragma unroll
            for (int mt = 0; mt < 4; mt++)
#pragma unroll
                for (int nt = 0; nt < 4; nt++) {
                    mma_bf16(acc[mt][nt], ah[mt], bh[nt]);
                    mma_bf16(acc[mt][nt], ah[mt], bl[nt]);
                    mma_bf16(acc[mt][nt], al[mt], bh[nt]);
                }
        }
        if (have_next) {
            STORE_S(cur ^ 1);
            __syncthreads();
        }
    }

    // epilogue
#pragma unroll
    for (int mt = 0; mt < 4; mt++) {
        int r0 = rbase + wm * 64 + mt * 16 + (lane >> 2);
#pragma unroll
        for (int half = 0; half < 2; half++) {
            int r = r0 + half * 8;
            if (r >= rowEnd) continue;
            float sc = rowscale ? rowscale[r] : 1.f;
            long long rb = (long long)r * ldc;
#pragma unroll
            for (int nt = 0; nt < 4; nt++) {
                int c = cbase + wn * 32 + nt * 8 + (lane & 3) * 2;
                float v0 = acc[mt][nt][half * 2 + 0] * sc;
                float v1 = acc[mt][nt][half * 2 + 1] * sc;
                if (addsrc) { v0 += addsrc[rb + c]; v1 += addsrc[rb + c + 1]; }
                C[rb + c] = v0;
                C[rb + c + 1] = v1;
                if (Cdup) { Cdup[rb + c] = v0; Cdup[rb + c + 1] = v1; }
            }
        }
    }
}

// ---------------- embed lookup + rms -> concat (bf16 split out) ----------------
__global__ void embcat_kernel(const int* __restrict__ ids,
                              const float* __restrict__ emb_w,
                              const float* __restrict__ hid,
                              const float* __restrict__ we,
                              const float* __restrict__ wh) {
    int t = blockIdx.x;
    const float* er = emb_w + (size_t)ids[t] * H_;
    const float* hr = hid + (size_t)t * H_;
    __nv_bfloat16* ch = ab_h + AOFF_CAT + (size_t)t * 2 * H_;
    __nv_bfloat16* cl = ab_l + AOFF_CAT + (size_t)t * 2 * H_;
    float ss = 0.f;
    for (int h = threadIdx.x; h < H_; h += blockDim.x) { float v = er[h]; ss += v * v; }
    float tot = block_reduce_sum(ss);
    float rs = rsqrtf(tot / H_ + EPS_);
    for (int h = threadIdx.x; h < H_; h += blockDim.x)
        split1(er[h] * rs * (1.f + we[h]), ch + h, cl + h);
    ss = 0.f;
    for (int h = threadIdx.x; h < H_; h += blockDim.x) { float v = hr[h]; ss += v * v; }
    tot = block_reduce_sum(ss);
    rs = rsqrtf(tot / H_ + EPS_);
    for (int h = threadIdx.x; h < H_; h += blockDim.x)
        split1(hr[h] * rs * (1.f + wh[h]), ch + H_ + h, cl + H_ + h);
}

// ---------------- row RMS norm -> float + bf16 split ----------------
__global__ void rmsnorm_kernel(const float* __restrict__ in,
                               const float* __restrict__ w,
                               float* __restrict__ outf,
                               __nv_bfloat16* __restrict__ outh,
                               __nv_bfloat16* __restrict__ outl) {
    int t = blockIdx.x;
    const float* r = in + (size_t)t * H_;
    float ss = 0.f;
    for (int h = threadIdx.x; h < H_; h += blockDim.x) { float v = r[h]; ss += v * v; }
    float tot = block_reduce_sum(ss);
    float rs = rsqrtf(tot / H_ + EPS_);
    for (int h = threadIdx.x; h < H_; h += blockDim.x) {
        float v = r[h] * rs * (1.f + w[h]);
        outf[(size_t)t * H_ + h] = v;
        split1(v, outh + (size_t)t * H_ + h, outl + (size_t)t * H_ + h);
    }
}

// ---------------- per-head rms + rope (in place) ----------------
__global__ void qkrope_kernel(float* __restrict__ x, int nheads,
                              const float* __restrict__ nw,
                              const int* __restrict__ positions) {
    int t = blockIdx.x, h = blockIdx.y;
    float* v = x + ((size_t)t * nheads + h) * DH_;
    int d = threadIdx.x;
    float val = v[d];
    float ss = val * val;
#pragma unroll
    for (int o = 16; o > 0; o >>= 1) ss += __shfl_xor_sync(0xffffffffu, ss, o);
    __shared__ float ws[4];
    if ((d & 31) == 0) ws[d >> 5] = ss;
    __syncthreads();
    float tot = ws[0] + ws[1] + ws[2] + ws[3];
    float rs = rsqrtf(tot / DH_ + EPS_);
    float n = val * rs * (1.f + nw[d]);
    __shared__ float nv[DH_];
    nv[d] = n;
    __syncthreads();
    int pos = positions[t];
    int i = d & 63;
    float inv = expf(-((float)i / 64.f) * 13.815510557964274f);
    float ang = (float)pos * inv;
    float c = cosf(ang), s = sinf(ang);
    float outv;
    if (d < 64) outv = nv[d] * c - nv[d + 64] * s;
    else        outv = nv[d] * c + nv[d - 64] * s;
    v[d] = outv;
}

// ---------------- flash attention (causal, GQA); bf16-split output ----------------
__global__ void attn_kernel(const int* __restrict__ positions) {
    int qt = blockIdx.x, h = blockIdx.y;
    int tid = threadIdx.x;
    int qr = tid >> 2, quad = tid & 3;
    int qrow = qt * 32 + qr;
    int kvh = h >> 2;

    __shared__ __align__(16) float4 Ks[32][32];
    __shared__ __align__(16) float4 Vs[32][32];
    __shared__ float S[32][33];
    __shared__ float mrow[32], lrow[32], arow[32];
    __shared__ int kpos_s[32];

    float4 qv[8];
    const float* qp = g_q + ((size_t)qrow * NH_ + h) * DH_ + quad * 32;
#pragma unroll
    for (int i = 0; i < 8; i++) qv[i] = *reinterpret_cast<const float4*>(qp + i * 4);

    if (quad == 0) { mrow[qr] = -1e30f; lrow[qr] = 0.f; }
    float acc[32];
#pragma unroll
    for (int i = 0; i < 32; i++) acc[i] = 0.f;
    int qpos = positions[qrow];
    const float scale = 0.08838834764831845f;

    for (int kt = 0; kt <= qt; kt++) {
        __syncthreads();
        for (int ii = tid; ii < 32 * 32; ii += 128) {
            int kr = ii >> 5, c = ii & 31;
            size_t base = ((size_t)(kt * 32 + kr) * NKV_ + kvh) * DH_;
            Ks[kr][c] = *reinterpret_cast<const float4*>(g_k + base + c * 4);
            Vs[kr][c] = *reinterpret_cast<const float4*>(g_v + base + c * 4);
        }
        if (tid < 32) kpos_s[tid] = positions[kt * 32 + tid];
        __syncthreads();
        for (int kr = 0; kr < 32; kr++) {
            float p = 0.f;
#pragma unroll
            for (int i = 0; i < 8; i++) {
                float4 kk = Ks[kr][quad * 8 + i];
                p += qv[i].x * kk.x + qv[i].y * kk.y + qv[i].z * kk.z + qv[i].w * kk.w;
            }
            p += __shfl_xor_sync(0xffffffffu, p, 1);
            p += __shfl_xor_sync(0xffffffffu, p, 2);
            if (quad == 0)
                S[qr][kr] = (kpos_s[kr] <= qpos) ? p * scale : -1e30f;
        }
        __syncthreads();
        if (tid < 32) {
            int r = tid;
            float mold = mrow[r], mx = mold;
            for (int kr = 0; kr < 32; kr++) mx = fmaxf(mx, S[r][kr]);
            float al = expf(mold - mx);
            float rsum = 0.f;
            for (int kr = 0; kr < 32; kr++) {
                float pe = expf(S[r][kr] - mx);
                S[r][kr] = pe;
                rsum += pe;
            }
            mrow[r] = mx;
            lrow[r] = lrow[r] * al + rsum;
            arow[r] = al;
        }
        __syncthreads();
        float al = arow[qr];
#pragma unroll
        for (int i = 0; i < 32; i++) acc[i] *= al;
        for (int kr = 0; kr < 32; kr++) {
            float w = S[qr][kr];
#pragma unroll
            for (int i = 0; i < 8; i++) {
                float4 vv = Vs[kr][quad * 8 + i];
                acc[i * 4 + 0] += w * vv.x;
                acc[i * 4 + 1] += w * vv.y;
                acc[i * 4 + 2] += w * vv.z;
                acc[i * 4 + 3] += w * vv.w;
            }
        }
    }
    float inv_l = 1.f / lrow[qr];
    size_t obase = (size_t)qrow * (NH_ * DH_) + h * DH_ + quad * 32;
    __nv_bfloat16* oh = ab_h + AOFF_ATTN + obase;
    __nv_bfloat16* ol = ab_l + AOFF_ATTN + obase;
#pragma unroll
    for (int i = 0; i < 32; i++) split1(acc[i] * inv_l, oh + i, ol + i);
}

// ---------------- router ----------------
__global__ void zero_counts_kernel() {
    if (threadIdx.x < E_) g_counts[threadIdx.x] = 0;
}

__global__ void router_kernel(const float* __restrict__ rw) {
    int t = blockIdx.x;
    __shared__ float part[256];
    __shared__ float logits[E_];
    int tid = threadIdx.x;
    int e = tid >> 4, c = tid & 15;
    float s = 0.f;
    const float* xr = g_xn + (size_t)t * H_;
    for (int h = c * 128; h < (c + 1) * 128; h++) s += xr[h] * rw[(size_t)h * E_ + e];
    part[tid] = s;
    __syncthreads();
    if (c == 0) {
        float tot = 0.f;
        for (int i = 0; i < 16; i++) tot += part[e * 16 + i];
        logits[e] = tot;
    }
    __syncthreads();
    if (tid == 0) {
        float mx = -1e30f;
        for (int i = 0; i < E_; i++) mx = fmaxf(mx, logits[i]);
        float p[E_];
        for (int i = 0; i < E_; i++) p[i] = expf(logits[i] - mx);
        int i0 = 0; float v0 = p[0];
        for (int i = 1; i < E_; i++) if (p[i] > v0) { v0 = p[i]; i0 = i; }
        int i1 = -1; float v1 = -1.f;
        for (int i = 0; i < E_; i++) if (i != i0 && p[i] > v1) { v1 = p[i]; i1 = i; }
        float denom = v0 + v1;
        g_top_idx[t * 2 + 0] = i0;
        g_top_idx[t * 2 + 1] = i1;
        g_top_w[t * 2 + 0] = v0 / denom;
        g_top_w[t * 2 + 1] = v1 / denom;
        atomicAdd(&g_counts[i0], 1);
        atomicAdd(&g_counts[i1], 1);
    }
}

__global__ void offsets_kernel() {
    if (threadIdx.x == 0) {
        int acc = 0;
        for (int e = 0; e < E_; e++) { g_offs[e] = acc; acc += g_counts[e]; }
        g_offs[E_] = acc;
    }
    if (threadIdx.x < E_) g_counts2[threadIdx.x] = 0;
}

__global__ void scatter_kernel() {
    int t = blockIdx.x * blockDim.x + threadIdx.x;
    if (t >= T_) return;
    for (int k = 0; k < TOPK_; k++) {
        int e = g_top_idx[t * 2 + k];
        int pos = atomicAdd(&g_counts2[e], 1);
        int slot = g_offs[e] + pos;
        g_tok_of_slot[slot] = t;
        g_gate_of_slot[slot] = g_top_w[t * 2 + k];
        g_slot_of_tok[t * 2 + k] = slot;
    }
}

// ---------------- silu(g)*u -> bf16 split ----------------
__global__ void silu_mul_kernel() {
    size_t i = (size_t)blockIdx.x * blockDim.x + threadIdx.x;
    if (i >= (size_t)T_ * TOPK_ * I_) return;
    float x = g_gbuf[i];
    float v = (x / (1.f + expf(-x))) * g_ubuf[i];
    split1(v, ab_h + AOFF_ACT + i, ab_l + AOFF_ACT + i);
}

// ---------------- final combine + rms ----------------
__global__ void final_kernel(const float* __restrict__ fw, float* __restrict__ out) {
    int t = blockIdx.x;
    __shared__ float buf[H_];
    int s0 = g_slot_of_tok[t * 2 + 0];
    int s1 = g_slot_of_tok[t * 2 + 1];
    float ss = 0.f;
    for (int h = threadIdx.x; h < H_; h += blockDim.x) {
        float v = g_x[(size_t)t * H_ + h] + g_downbuf[(size_t)s0 * H_ + h] +
                  g_downbuf[(size_t)s1 * H_ + h];
        buf[h] = v;
        ss += v * v;
    }
    float tot = block_reduce_sum(ss);
    float rs = rsqrtf(tot / H_ + EPS_);
    for (int h = threadIdx.x; h < H_; h += blockDim.x)
        out[(size_t)t * H_ + h] = buf[h] * rs * (1.f + fw[h]);
}

// ---------------- launch ----------------
extern "C" void kernel_launch(void* const* d_in, const int* in_sizes, int n_in,
                              void* d_out, int out_size) {
    const int* input_ids      = (const int*)d_in[0];
    const int* positions      = (const int*)d_in[1];
    const float* hidden       = (const float*)d_in[2];
    const float* embed_w      = (const float*)d_in[4];
    const float* fc_w         = (const float*)d_in[5];
    const float* pre_fc_emb_w = (const float*)d_in[6];
    const float* pre_fc_hid_w = (const float*)d_in[7];
    const float* in_ln_w      = (const float*)d_in[8];
    const float* post_ln_w    = (const float*)d_in[9];
    const float* final_norm_w = (const float*)d_in[10];
    const float* wo           = (const float*)d_in[14];
    const float* q_norm_w     = (const float*)d_in[15];
    const float* k_norm_w     = (const float*)d_in[16];
    const float* router_w     = (const float*)d_in[17];
    float* out = (float*)d_out;

    float *p_x, *p_res, *p_xn, *p_q, *p_k, *p_v, *p_g, *p_u, *p_down, *p_gate;
    int *p_tok, *p_offs;
    __nv_bfloat16 *p_wh, *p_wl, *p_ah, *p_al;
    cudaGetSymbolAddress((void**)&p_x, g_x);
    cudaGetSymbolAddress((void**)&p_res, g_res);
    cudaGetSymbolAddress((void**)&p_xn, g_xn);
    cudaGetSymbolAddress((void**)&p_q, g_q);
    cudaGetSymbolAddress((void**)&p_k, g_k);
    cudaGetSymbolAddress((void**)&p_v, g_v);
    cudaGetSymbolAddress((void**)&p_g, g_gbuf);
    cudaGetSymbolAddress((void**)&p_u, g_ubuf);
    cudaGetSymbolAddress((void**)&p_down, g_downbuf);
    cudaGetSymbolAddress((void**)&p_gate, g_gate_of_slot);
    cudaGetSymbolAddress((void**)&p_tok, g_tok_of_slot);
    cudaGetSymbolAddress((void**)&p_offs, g_offs);
    cudaGetSymbolAddress((void**)&p_wh, wb_h);
    cudaGetSymbolAddress((void**)&p_wl, wb_l);
    cudaGetSymbolAddress((void**)&p_ah, ab_h);
    cudaGetSymbolAddress((void**)&p_al, ab_l);

    cudaFuncSetAttribute(gemm_mma, cudaFuncAttributeMaxDynamicSharedMemorySize,
                         GSMEM_BYTES);

    // ---- weight split conversions (every call; weights are inputs) ----
    struct WCvt { const float* src; long long off, n; };
    const WCvt wc[8] = {
        {fc_w,                 WOFF_FC, 8388608LL},
        {(const float*)d_in[11], WOFF_Q, 4194304LL},
        {(const float*)d_in[12], WOFF_K, 1048576LL},
        {(const float*)d_in[13], WOFF_V, 1048576LL},
        {wo,                   WOFF_O, 4194304LL},
        {(const float*)d_in[18], WOFF_G, 33554432LL},
        {(const float*)d_in[19], WOFF_U, 33554432LL},
        {(const float*)d_in[20], WOFF_D, 33554432LL},
    };
    for (int i = 0; i < 8; i++) {
        long long nthr = wc[i].n / 4;
        cvt_split<<<(unsigned)((nthr + 255) / 256), 256>>>(wc[i].src, p_wh + wc[i].off,
                                                           p_wl + wc[i].off, wc[i].n);
    }

    // 1. embed + rms -> concat (bf16 split)
    embcat_kernel<<<T_, 256>>>(input_ids, embed_w, hidden, pre_fc_emb_w, pre_fc_hid_w);

    // 2. fc: x = cat @ fc_w ; residual = x
    gemm_mma<<<dim3(H_ / 128, T_ / 128), 256, GSMEM_BYTES>>>(
        p_ah + AOFF_CAT, p_al + AOFF_CAT, p_wh + WOFF_FC, p_wl + WOFF_FC, p_x,
        T_, H_, 2 * H_, 2 * H_, H_, H_, nullptr, nullptr, p_res, nullptr, 0, nullptr);

    // 3. in_ln
    rmsnorm_kernel<<<T_, 256>>>(p_x, in_ln_w, p_xn, p_ah + AOFF_XN, p_al + AOFF_XN);

    // 4. qkv
    gemm_mma<<<dim3((NH_ * DH_) / 128, T_ / 128), 256, GSMEM_BYTES>>>(
        p_ah + AOFF_XN, p_al + AOFF_XN, p_wh + WOFF_Q, p_wl + WOFF_Q, p_q,
        T_, NH_ * DH_, H_, H_, NH_ * DH_, NH_ * DH_, nullptr, nullptr, nullptr, nullptr, 0, nullptr);
    gemm_mma<<<dim3((NKV_ * DH_) / 128, T_ / 128), 256, GSMEM_BYTES>>>(
        p_ah + AOFF_XN, p_al + AOFF_XN, p_wh + WOFF_K, p_wl + WOFF_K, p_k,
        T_, NKV_ * DH_, H_, H_, NKV_ * DH_, NKV_ * DH_, nullptr, nullptr, nullptr, nullptr, 0, nullptr);
    gemm_mma<<<dim3((NKV_ * DH_) / 128, T_ / 128), 256, GSMEM_BYTES>>>(
        p_ah + AOFF_XN, p_al + AOFF_XN, p_wh + WOFF_V, p_wl + WOFF_V, p_v,
        T_, NKV_ * DH_, H_, H_, NKV_ * DH_, NKV_ * DH_, nullptr, nullptr, nullptr, nullptr, 0, nullptr);

    // 5. q/k norm + rope
    qkrope_kernel<<<dim3(T_, NH_), DH_>>>(p_q, NH_, q_norm_w, positions);
    qkrope_kernel<<<dim3(T_, NKV_), DH_>>>(p_k, NKV_, k_norm_w, positions);

    // 6. attention -> bf16 split attn buffer
    attn_kernel<<<dim3(T_ / 32, NH_), 128>>>(positions);

    // 7. wo + residual -> x
    gemm_mma<<<dim3(H_ / 128, T_ / 128), 256, GSMEM_BYTES>>>(
        p_ah + AOFF_ATTN, p_al + AOFF_ATTN, p_wh + WOFF_O, p_wl + WOFF_O, p_x,
        T_, H_, NH_ * DH_, NH_ * DH_, H_, H_, nullptr, p_res, nullptr, nullptr, 0, nullptr);

    // 8. post_ln
    rmsnorm_kernel<<<T_, 256>>>(p_x, post_ln_w, p_xn, p_ah + AOFF_XN, p_al + AOFF_XN);

    // 9. router + bucketing
    zero_counts_kernel<<<1, 32>>>();
    router_kernel<<<T_, 256>>>(router_w);
    offsets_kernel<<<1, 32>>>();
    scatter_kernel<<<(T_ + 255) / 256, 256>>>();

    // 10. MoE grouped GEMMs
    gemm_mma<<<dim3(I_ / 128, T_ / 128, E_), 256, GSMEM_BYTES>>>(
        p_ah + AOFF_XN, p_al + AOFF_XN, p_wh + WOFF_G, p_wl + WOFF_G, p_g,
        0, I_, H_, H_, I_, I_, p_tok, nullptr, nullptr, p_offs, (long long)H_ * I_, nullptr);
    gemm_mma<<<dim3(I_ / 128, T_ / 128, E_), 256, GSMEM_BYTES>>>(
        p_ah + AOFF_XN, p_al + AOFF_XN, p_wh + WOFF_U, p_wl + WOFF_U, p_u,
        0, I_, H_, H_, I_, I_, p_tok, nullptr, nullptr, p_offs, (long long)H_ * I_, nullptr);
    silu_mul_kernel<<<((size_t)T_ * TOPK_ * I_ + 255) / 256, 256>>>();
    gemm_mma<<<dim3(H_ / 128, T_ / 128, E_), 256, GSMEM_BYTES>>>(
        p_ah + AOFF_ACT, p_al + AOFF_ACT, p_wh + WOFF_D, p_wl + WOFF_D, p_down,
        0, H_, I_, I_, H_, H_, nullptr, nullptr, nullptr, p_offs, (long long)I_ * H_, p_gate);

    // 11. combine + final rms
    final_kernel<<<T_, 256>>>(final_norm_w, out);
}

// round 4
// speedup vs baseline: 1.5459x; 1.5459x over previous
#include <cuda_runtime.h>
#include <math.h>

#define T_ 2048
#define H_ 2048
#define NH_ 16
#define NKV_ 4
#define DH_ 128
#define E_ 16
#define TOPK_ 2
#define I_ 1024
#define EPS_ 1e-6f

// ---------------- scratch ----------------
__device__ float g_cat[(size_t)T_ * 2 * H_];
__device__ float g_x[(size_t)T_ * H_];
__device__ float g_res[(size_t)T_ * H_];
__device__ float g_xn[(size_t)T_ * H_];
__device__ float g_q[(size_t)T_ * NH_ * DH_];
__device__ float g_k[(size_t)T_ * NKV_ * DH_];
__device__ float g_v[(size_t)T_ * NKV_ * DH_];
__device__ float g_attn[(size_t)T_ * NH_ * DH_];
__device__ float g_gbuf[(size_t)T_ * TOPK_ * I_];
__device__ float g_ubuf[(size_t)T_ * TOPK_ * I_];
__device__ float g_downbuf[(size_t)T_ * TOPK_ * H_];
__device__ int   g_top_idx[T_ * TOPK_];
__device__ float g_top_w[T_ * TOPK_];
__device__ int   g_counts[E_];
__device__ int   g_counts2[E_];
__device__ int   g_offs[E_ + 1];
__device__ int   g_tok_of_slot[T_ * TOPK_];
__device__ float g_gate_of_slot[T_ * TOPK_];
__device__ int   g_slot_of_tok[T_ * TOPK_];

// ---------------- helpers ----------------
__device__ __forceinline__ float block_reduce_sum(float v) {
    __shared__ float sb[33];
    int tid = threadIdx.x;
#pragma unroll
    for (int o = 16; o > 0; o >>= 1) v += __shfl_xor_sync(0xffffffffu, v, o);
    if ((tid & 31) == 0) sb[tid >> 5] = v;
    __syncthreads();
    if (tid == 0) {
        float s = 0.f;
        int nw = (blockDim.x + 31) >> 5;
        for (int i = 0; i < nw; i++) s += sb[i];
        sb[32] = s;
    }
    __syncthreads();
    return sb[32];
}

// ---------------- fp32 SGEMM: 128x128 tile, 8x8 micro-tile, 256 threads ----------------
__global__ __launch_bounds__(256, 2)
void gemm128(const float* __restrict__ A, const float* __restrict__ B,
             float* __restrict__ C,
             int M, int N, int Kd, int lda, int ldb, int ldc,
             const int* __restrict__ rowmap,
             const float* __restrict__ addsrc,
             float* __restrict__ Cdup,
             const int* __restrict__ segoff,
             long long strideB,
             const float* __restrict__ rowscale) {
    int row0 = 0, rowEnd = M;
    const float* Bp = B;
    if (segoff) {
        int e = blockIdx.z;
        row0 = segoff[e];
        rowEnd = segoff[e + 1];
        Bp = B + (long long)e * strideB;
    }
    int rbase = row0 + blockIdx.y * 128;
    if (rbase >= rowEnd) return;
    int cbase = blockIdx.x * 128;

    __shared__ float As[16][132];   // transposed: As[k][m]
    __shared__ float Bs[16][132];   // Bs[k][n]

    int tid = threadIdx.x;
    int tx = tid & 15, ty = tid >> 4;

    // A staging map: m = tid&127, k-offset = (tid>>7)*8 (two float4 along k)
    int am = tid & 127;
    int ak0 = (tid >> 7) * 8;
    int arow_g = rbase + am;
    const float* Arow = nullptr;
    if (arow_g < rowEnd) {
        int m = rowmap ? rowmap[arow_g] : arow_g;
        Arow = A + (long long)m * lda;
    }
    // B staging map: r = tid>>5 (and +8), c4 = tid&31
    int br0 = tid >> 5;
    int bc4 = tid & 31;

    float acc[8][8];
#pragma unroll
    for (int i = 0; i < 8; i++)
#pragma unroll
        for (int j = 0; j < 8; j++) acc[i][j] = 0.f;

    float4 ra0, ra1, rb0, rb1;
    const float4 Z = make_float4(0.f, 0.f, 0.f, 0.f);

#define LOADG(K0)                                                                    \
    do {                                                                             \
        if (Arow) {                                                                  \
            ra0 = *(const float4*)(Arow + (K0) + ak0);                               \
            ra1 = *(const float4*)(Arow + (K0) + ak0 + 4);                           \
        } else { ra0 = Z; ra1 = Z; }                                                 \
        rb0 = *(const float4*)(Bp + (long long)((K0) + br0) * ldb + cbase + bc4 * 4);\
        rb1 = *(const float4*)(Bp + (long long)((K0) + br0 + 8) * ldb + cbase + bc4 * 4);\
    } while (0)

    int nk = Kd >> 4;
    LOADG(0);
    for (int kt = 0; kt < nk; kt++) {
        __syncthreads();
        As[ak0 + 0][am] = ra0.x; As[ak0 + 1][am] = ra0.y;
        As[ak0 + 2][am] = ra0.z; As[ak0 + 3][am] = ra0.w;
        As[ak0 + 4][am] = ra1.x; As[ak0 + 5][am] = ra1.y;
        As[ak0 + 6][am] = ra1.z; As[ak0 + 7][am] = ra1.w;
        *(float4*)&Bs[br0][bc4 * 4] = rb0;
        *(float4*)&Bs[br0 + 8][bc4 * 4] = rb1;
        __syncthreads();
        if (kt + 1 < nk) LOADG((kt + 1) * 16);
#pragma unroll
        for (int kk = 0; kk < 16; kk++) {
            float a[8], b[8];
            float4 t;
            t = *(const float4*)&As[kk][ty * 8];     a[0] = t.x; a[1] = t.y; a[2] = t.z; a[3] = t.w;
            t = *(const float4*)&As[kk][ty * 8 + 4]; a[4] = t.x; a[5] = t.y; a[6] = t.z; a[7] = t.w;
            t = *(const float4*)&Bs[kk][tx * 8];     b[0] = t.x; b[1] = t.y; b[2] = t.z; b[3] = t.w;
            t = *(const float4*)&Bs[kk][tx * 8 + 4]; b[4] = t.x; b[5] = t.y; b[6] = t.z; b[7] = t.w;
#pragma unroll
            for (int i = 0; i < 8; i++)
#pragma unroll
                for (int j = 0; j < 8; j++) acc[i][j] += a[i] * b[j];
        }
    }
#undef LOADG

#pragma unroll
    for (int i = 0; i < 8; i++) {
        int r = rbase + ty * 8 + i;
        if (r >= rowEnd) break;
        float sc = rowscale ? rowscale[r] : 1.f;
        long long base = (long long)r * ldc + cbase + tx * 8;
        float4 v0 = make_float4(acc[i][0] * sc, acc[i][1] * sc, acc[i][2] * sc, acc[i][3] * sc);
        float4 v1 = make_float4(acc[i][4] * sc, acc[i][5] * sc, acc[i][6] * sc, acc[i][7] * sc);
        if (addsrc) {
            float4 s0 = *(const float4*)(addsrc + base);
            float4 s1 = *(const float4*)(addsrc + base + 4);
            v0.x += s0.x; v0.y += s0.y; v0.z += s0.z; v0.w += s0.w;
            v1.x += s1.x; v1.y += s1.y; v1.z += s1.z; v1.w += s1.w;
        }
        *(float4*)(C + base) = v0;
        *(float4*)(C + base + 4) = v1;
        if (Cdup) {
            *(float4*)(Cdup + base) = v0;
            *(float4*)(Cdup + base + 4) = v1;
        }
    }
}

// ---------------- embed lookup + rms -> concat ----------------
__global__ void embcat_kernel(const int* __restrict__ ids,
                              const float* __restrict__ emb_w,
                              const float* __restrict__ hid,
                              const float* __restrict__ we,
                              const float* __restrict__ wh) {
    int t = blockIdx.x;
    const float* er = emb_w + (size_t)ids[t] * H_;
    const float* hr = hid + (size_t)t * H_;
    float ss = 0.f;
    for (int h = threadIdx.x; h < H_; h += blockDim.x) { float v = er[h]; ss += v * v; }
    float tot = block_reduce_sum(ss);
    float rs = rsqrtf(tot / H_ + EPS_);
    for (int h = threadIdx.x; h < H_; h += blockDim.x)
        g_cat[(size_t)t * 2 * H_ + h] = er[h] * rs * (1.f + we[h]);
    ss = 0.f;
    for (int h = threadIdx.x; h < H_; h += blockDim.x) { float v = hr[h]; ss += v * v; }
    tot = block_reduce_sum(ss);
    rs = rsqrtf(tot / H_ + EPS_);
    for (int h = threadIdx.x; h < H_; h += blockDim.x)
        g_cat[(size_t)t * 2 * H_ + H_ + h] = hr[h] * rs * (1.f + wh[h]);
}

// ---------------- row RMS norm ----------------
__global__ void rmsnorm_kernel(const float* __restrict__ in,
                               const float* __restrict__ w,
                               float* __restrict__ out) {
    int t = blockIdx.x;
    const float* r = in + (size_t)t * H_;
    float ss = 0.f;
    for (int h = threadIdx.x; h < H_; h += blockDim.x) { float v = r[h]; ss += v * v; }
    float tot = block_reduce_sum(ss);
    float rs = rsqrtf(tot / H_ + EPS_);
    for (int h = threadIdx.x; h < H_; h += blockDim.x)
        out[(size_t)t * H_ + h] = r[h] * rs * (1.f + w[h]);
}

// ---------------- per-head rms + rope (in place) ----------------
__global__ void qkrope_kernel(float* __restrict__ x, int nheads,
                              const float* __restrict__ nw,
                              const int* __restrict__ positions) {
    int t = blockIdx.x, h = blockIdx.y;
    float* v = x + ((size_t)t * nheads + h) * DH_;
    int d = threadIdx.x;
    float val = v[d];
    float ss = val * val;
#pragma unroll
    for (int o = 16; o > 0; o >>= 1) ss += __shfl_xor_sync(0xffffffffu, ss, o);
    __shared__ float ws[4];
    if ((d & 31) == 0) ws[d >> 5] = ss;
    __syncthreads();
    float tot = ws[0] + ws[1] + ws[2] + ws[3];
    float rs = rsqrtf(tot / DH_ + EPS_);
    float n = val * rs * (1.f + nw[d]);
    __shared__ float nv[DH_];
    nv[d] = n;
    __syncthreads();
    int pos = positions[t];
    int i = d & 63;
    float inv = expf(-((float)i / 64.f) * 13.815510557964274f);
    float ang = (float)pos * inv;
    float c = cosf(ang), s = sinf(ang);
    float outv;
    if (d < 64) outv = nv[d] * c - nv[d + 64] * s;
    else        outv = nv[d] * c + nv[d - 64] * s;
    v[d] = outv;
}

// ---------------- flash attention, parallel softmax ----------------
// grid (T/32, NH), block 128. thread: qr = tid>>2 (q-row), c = tid&3 (quad).
// Thread owns output dims {(i*4+c)*4 .. +3 : i=0..7} of its q-row.
#define QP 132   // float pitch for Q/K/V tiles
#define ATT_SMEM ((3 * 32 * QP + 32 * 33 + 32) * 4)
__global__ __launch_bounds__(128)
void attn_kernel(const int* __restrict__ positions) {
    int qt = blockIdx.x, h = blockIdx.y;
    int tid = threadIdx.x;
    int qr = tid >> 2, c = tid & 3;
    int qrow = qt * 32 + qr;
    int kvh = h >> 2;

    extern __shared__ float sma[];
    float* Qs = sma;                  // 32 x QP
    float* Ks = Qs + 32 * QP;
    float* Vs = Ks + 32 * QP;
    float* Ps = Vs + 32 * QP;         // 32 x 33
    int* kpos_s = (int*)(Ps + 32 * 33);

    // load Q tile
    for (int ii = tid; ii < 32 * 32; ii += 128) {
        int r = ii >> 5, d4 = ii & 31;
        *(float4*)&Qs[r * QP + d4 * 4] =
            *(const float4*)(g_q + ((size_t)(qt * 32 + r) * NH_ + h) * DH_ + d4 * 4);
    }
    int qpos = positions[qrow];
    float m_run = -1e30f, l_run = 0.f;
    float acc[32];
#pragma unroll
    for (int i = 0; i < 32; i++) acc[i] = 0.f;
    const float scale = 0.08838834764831845f;

    for (int kt = 0; kt <= qt; kt++) {
        __syncthreads();
        for (int ii = tid; ii < 32 * 32; ii += 128) {
            int r = ii >> 5, d4 = ii & 31;
            size_t base = ((size_t)(kt * 32 + r) * NKV_ + kvh) * DH_ + d4 * 4;
            *(float4*)&Ks[r * QP + d4 * 4] = *(const float4*)(g_k + base);
            *(float4*)&Vs[r * QP + d4 * 4] = *(const float4*)(g_v + base);
        }
        if (tid < 32) kpos_s[tid] = positions[kt * 32 + tid];
        __syncthreads();

        // scores: thread computes 8 full dots for kr = c*8 + j
        float s[8];
#pragma unroll
        for (int j = 0; j < 8; j++) s[j] = 0.f;
        for (int d4 = 0; d4 < 32; d4++) {
            float4 q4 = *(const float4*)&Qs[qr * QP + d4 * 4];
#pragma unroll
            for (int j = 0; j < 8; j++) {
                float4 k4 = *(const float4*)&Ks[(c * 8 + j) * QP + d4 * 4];
                s[j] += q4.x * k4.x + q4.y * k4.y + q4.z * k4.z + q4.w * k4.w;
            }
        }
#pragma unroll
        for (int j = 0; j < 8; j++) {
            int kr = c * 8 + j;
            s[j] = (kpos_s[kr] <= qpos) ? s[j] * scale : -1e30f;
        }
        // quad-parallel softmax update
        float mx = s[0];
#pragma unroll
        for (int j = 1; j < 8; j++) mx = fmaxf(mx, s[j]);
        mx = fmaxf(mx, __shfl_xor_sync(0xffffffffu, mx, 1));
        mx = fmaxf(mx, __shfl_xor_sync(0xffffffffu, mx, 2));
        mx = fmaxf(mx, m_run);
        float al = expf(m_run - mx);
        float rsum = 0.f;
#pragma unroll
        for (int j = 0; j < 8; j++) {
            s[j] = expf(s[j] - mx);
            rsum += s[j];
        }
        rsum += __shfl_xor_sync(0xffffffffu, rsum, 1);
        rsum += __shfl_xor_sync(0xffffffffu, rsum, 2);
        m_run = mx;
        l_run = l_run * al + rsum;
#pragma unroll
        for (int j = 0; j < 8; j++) Ps[qr * 33 + c * 8 + j] = s[j];
#pragma unroll
        for (int i = 0; i < 32; i++) acc[i] *= al;
        __syncthreads();
        // PV: thread accumulates its quad-interleaved dims
        for (int kr = 0; kr < 32; kr++) {
            float w = Ps[qr * 33 + kr];
#pragma unroll
            for (int i = 0; i < 8; i++) {
                float4 v4 = *(const float4*)&Vs[kr * QP + (i * 4 + c) * 4];
                acc[i * 4 + 0] += w * v4.x;
                acc[i * 4 + 1] += w * v4.y;
                acc[i * 4 + 2] += w * v4.z;
                acc[i * 4 + 3] += w * v4.w;
            }
        }
    }
    float inv_l = 1.f / l_run;
    float* orow = g_attn + (size_t)qrow * (NH_ * DH_) + h * DH_;
#pragma unroll
    for (int i = 0; i < 8; i++) {
        float4 o = make_float4(acc[i * 4 + 0] * inv_l, acc[i * 4 + 1] * inv_l,
                               acc[i * 4 + 2] * inv_l, acc[i * 4 + 3] * inv_l);
        *(float4*)(orow + (i * 4 + c) * 4) = o;
    }
}

// ---------------- router ----------------
__global__ void zero_counts_kernel() {
    if (threadIdx.x < E_) g_counts[threadIdx.x] = 0;
}

__global__ void router_kernel(const float* __restrict__ rw) {
    int t = blockIdx.x;
    __shared__ float part[256];
    __shared__ float logits[E_];
    int tid = threadIdx.x;
    int e = tid >> 4, c = tid & 15;
    float s = 0.f;
    const float* xr = g_xn + (size_t)t * H_;
    for (int h = c * 128; h < (c + 1) * 128; h++) s += xr[h] * rw[(size_t)h * E_ + e];
    part[tid] = s;
    __syncthreads();
    if (c == 0) {
        float tot = 0.f;
        for (int i = 0; i < 16; i++) tot += part[e * 16 + i];
        logits[e] = tot;
    }
    __syncthreads();
    if (tid == 0) {
        float mx = -1e30f;
        for (int i = 0; i < E_; i++) mx = fmaxf(mx, logits[i]);
        float p[E_];
        for (int i = 0; i < E_; i++) p[i] = expf(logits[i] - mx);
        int i0 = 0; float v0 = p[0];
        for (int i = 1; i < E_; i++) if (p[i] > v0) { v0 = p[i]; i0 = i; }
        int i1 = -1; float v1 = -1.f;
        for (int i = 0; i < E_; i++) if (i != i0 && p[i] > v1) { v1 = p[i]; i1 = i; }
        float denom = v0 + v1;
        g_top_idx[t * 2 + 0] = i0;
        g_top_idx[t * 2 + 1] = i1;
        g_top_w[t * 2 + 0] = v0 / denom;
        g_top_w[t * 2 + 1] = v1 / denom;
        atomicAdd(&g_counts[i0], 1);
        atomicAdd(&g_counts[i1], 1);
    }
}

__global__ void offsets_kernel() {
    if (threadIdx.x == 0) {
        int acc = 0;
        for (int e = 0; e < E_; e++) { g_offs[e] = acc; acc += g_counts[e]; }
        g_offs[E_] = acc;
    }
    if (threadIdx.x < E_) g_counts2[threadIdx.x] = 0;
}

__global__ void scatter_kernel() {
    int t = blockIdx.x * blockDim.x + threadIdx.x;
    if (t >= T_) return;
    for (int k = 0; k < TOPK_; k++) {
        int e = g_top_idx[t * 2 + k];
        int pos = atomicAdd(&g_counts2[e], 1);
        int slot = g_offs[e] + pos;
        g_tok_of_slot[slot] = t;
        g_gate_of_slot[slot] = g_top_w[t * 2 + k];
        g_slot_of_tok[t * 2 + k] = slot;
    }
}

// ---------------- silu(g)*u in place ----------------
__global__ void silu_mul_kernel() {
    size_t i = (size_t)blockIdx.x * blockDim.x + threadIdx.x;
    if (i >= (size_t)T_ * TOPK_ * I_) return;
    float x = g_gbuf[i];
    g_gbuf[i] = (x / (1.f + expf(-x))) * g_ubuf[i];
}

// ---------------- final combine + rms ----------------
__global__ void final_kernel(const float* __restrict__ fw, float* __restrict__ out) {
    int t = blockIdx.x;
    __shared__ float buf[H_];
    int s0 = g_slot_of_tok[t * 2 + 0];
    int s1 = g_slot_of_tok[t * 2 + 1];
    float ss = 0.f;
    for (int h = threadIdx.x; h < H_; h += blockDim.x) {
        float v = g_x[(size_t)t * H_ + h] + g_downbuf[(size_t)s0 * H_ + h] +
                  g_downbuf[(size_t)s1 * H_ + h];
        buf[h] = v;
        ss += v * v;
    }
    float tot = block_reduce_sum(ss);
    float rs = rsqrtf(tot / H_ + EPS_);
    for (int h = threadIdx.x; h < H_; h += blockDim.x)
        out[(size_t)t * H_ + h] = buf[h] * rs * (1.f + fw[h]);
}

// ---------------- launch ----------------
extern "C" void kernel_launch(void* const* d_in, const int* in_sizes, int n_in,
                              void* d_out, int out_size) {
    const int* input_ids      = (const int*)d_in[0];
    const int* positions      = (const int*)d_in[1];
    const float* hidden       = (const float*)d_in[2];
    const float* embed_w      = (const float*)d_in[4];
    const float* fc_w         = (const float*)d_in[5];
    const float* pre_fc_emb_w = (const float*)d_in[6];
    const float* pre_fc_hid_w = (const float*)d_in[7];
    const float* in_ln_w      = (const float*)d_in[8];
    const float* post_ln_w    = (const float*)d_in[9];
    const float* final_norm_w = (const float*)d_in[10];
    const float* wq           = (const float*)d_in[11];
    const float* wk           = (const float*)d_in[12];
    const float* wv           = (const float*)d_in[13];
    const float* wo           = (const float*)d_in[14];
    const float* q_norm_w     = (const float*)d_in[15];
    const float* k_norm_w     = (const float*)d_in[16];
    const float* router_w     = (const float*)d_in[17];
    const float* w_gate       = (const float*)d_in[18];
    const float* w_up         = (const float*)d_in[19];
    const float* w_down       = (const float*)d_in[20];
    float* out = (float*)d_out;

    float *p_cat, *p_x, *p_res, *p_xn, *p_q, *p_k, *p_v, *p_attn, *p_g, *p_u, *p_down, *p_gate;
    int *p_tok, *p_offs;
    cudaGetSymbolAddress((void**)&p_cat, g_cat);
    cudaGetSymbolAddress((void**)&p_x, g_x);
    cudaGetSymbolAddress((void**)&p_res, g_res);
    cudaGetSymbolAddress((void**)&p_xn, g_xn);
    cudaGetSymbolAddress((void**)&p_q, g_q);
    cudaGetSymbolAddress((void**)&p_k, g_k);
    cudaGetSymbolAddress((void**)&p_v, g_v);
    cudaGetSymbolAddress((void**)&p_attn, g_attn);
    cudaGetSymbolAddress((void**)&p_g, g_gbuf);
    cudaGetSymbolAddress((void**)&p_u, g_ubuf);
    cudaGetSymbolAddress((void**)&p_down, g_downbuf);
    cudaGetSymbolAddress((void**)&p_gate, g_gate_of_slot);
    cudaGetSymbolAddress((void**)&p_tok, g_tok_of_slot);
    cudaGetSymbolAddress((void**)&p_offs, g_offs);

    cudaFuncSetAttribute(attn_kernel, cudaFuncAttributeMaxDynamicSharedMemorySize,
                         ATT_SMEM);

    // 1. embed + rms -> concat
    embcat_kernel<<<T_, 256>>>(input_ids, embed_w, hidden, pre_fc_emb_w, pre_fc_hid_w);

    // 2. fc: x = cat @ fc_w ; residual = x
    gemm128<<<dim3(H_ / 128, T_ / 128), 256>>>(p_cat, fc_w, p_x, T_, H_, 2 * H_,
                                               2 * H_, H_, H_, nullptr, nullptr, p_res,
                                               nullptr, 0, nullptr);

    // 3. in_ln
    rmsnorm_kernel<<<T_, 256>>>(p_x, in_ln_w, p_xn);

    // 4. qkv
    gemm128<<<dim3((NH_ * DH_) / 128, T_ / 128), 256>>>(p_xn, wq, p_q, T_, NH_ * DH_, H_,
                                                        H_, NH_ * DH_, NH_ * DH_,
                                                        nullptr, nullptr, nullptr, nullptr, 0, nullptr);
    gemm128<<<dim3((NKV_ * DH_) / 128, T_ / 128), 256>>>(p_xn, wk, p_k, T_, NKV_ * DH_, H_,
                                                         H_, NKV_ * DH_, NKV_ * DH_,
                                                         nullptr, nullptr, nullptr, nullptr, 0, nullptr);
    gemm128<<<dim3((NKV_ * DH_) / 128, T_ / 128), 256>>>(p_xn, wv, p_v, T_, NKV_ * DH_, H_,
                                                         H_, NKV_ * DH_, NKV_ * DH_,
                                                         nullptr, nullptr, nullptr, nullptr, 0, nullptr);

    // 5. q/k norm + rope
    qkrope_kernel<<<dim3(T_, NH_), DH_>>>(p_q, NH_, q_norm_w, positions);
    qkrope_kernel<<<dim3(T_, NKV_), DH_>>>(p_k, NKV_, k_norm_w, positions);

    // 6. attention
    attn_kernel<<<dim3(T_ / 32, NH_), 128, ATT_SMEM>>>(positions);

    // 7. wo + residual -> x
    gemm128<<<dim3(H_ / 128, T_ / 128), 256>>>(p_attn, wo, p_x, T_, H_, NH_ * DH_,
                                               NH_ * DH_, H_, H_, nullptr, p_res, nullptr,
                                               nullptr, 0, nullptr);

    // 8. post_ln
    rmsnorm_kernel<<<T_, 256>>>(p_x, post_ln_w, p_xn);

    // 9. router + bucketing
    zero_counts_kernel<<<1, 32>>>();
    router_kernel<<<T_, 256>>>(router_w);
    offsets_kernel<<<1, 32>>>();
    scatter_kernel<<<(T_ + 255) / 256, 256>>>();

    // 10. MoE grouped GEMMs (max rows per expert = T_ -> 16 y-blocks)
    gemm128<<<dim3(I_ / 128, T_ / 128, E_), 256>>>(p_xn, w_gate, p_g, 0, I_, H_,
                                                   H_, I_, I_, p_tok, nullptr, nullptr,
                                                   p_offs, (long long)H_ * I_, nullptr);
    gemm128<<<dim3(I_ / 128, T_ / 128, E_), 256>>>(p_xn, w_up, p_u, 0, I_, H_,
                                                   H_, I_, I_, p_tok, nullptr, nullptr,
                                                   p_offs, (long long)H_ * I_, nullptr);
    silu_mul_kernel<<<((size_t)T_ * TOPK_ * I_ + 255) / 256, 256>>>();
    gemm128<<<dim3(H_ / 128, T_ / 128, E_), 256>>>(p_g, w_down, p_down, 0, H_, I_,
                                                   I_, H_, H_, nullptr, nullptr, nullptr,
                                                   p_offs, (long long)I_ * H_, p_gate);

    // 11. combine + final rms
    final_kernel<<<T_, 256>>>(final_norm_w, out);
}

// round 5
// speedup vs baseline: 2.1385x; 1.3834x over previous
#include <cuda_runtime.h>
#include <math.h>

#define T_ 2048
#define H_ 2048
#define NH_ 16
#define NKV_ 4
#define DH_ 128
#define E_ 16
#define TOPK_ 2
#define I_ 1024
#define EPS_ 1e-6f

// ---------------- scratch ----------------
__device__ float g_cat[(size_t)T_ * 2 * H_];
__device__ float g_x[(size_t)T_ * H_];
__device__ float g_res[(size_t)T_ * H_];
__device__ float g_xn[(size_t)T_ * H_];
__device__ float g_qkv[(size_t)T_ * 3072];          // q[0:2048] k[2048:2560] v[2560:3072]
__device__ float g_attn[(size_t)T_ * NH_ * DH_];
__device__ float g_gbuf[(size_t)T_ * TOPK_ * I_];
__device__ float g_ubuf[(size_t)T_ * TOPK_ * I_];
__device__ float g_downbuf[(size_t)T_ * TOPK_ * H_];
__device__ int   g_top_idx[T_ * TOPK_];
__device__ float g_top_w[T_ * TOPK_];
__device__ int   g_counts[E_];
__device__ int   g_counts2[E_];
__device__ int   g_offs[E_ + 1];
__device__ int   g_tok_of_slot[T_ * TOPK_];
__device__ float g_gate_of_slot[T_ * TOPK_];
__device__ int   g_slot_of_tok[T_ * TOPK_];

// ---------------- helpers ----------------
__device__ __forceinline__ float block_reduce_sum(float v) {
    __shared__ float sb[33];
    int tid = threadIdx.x;
#pragma unroll
    for (int o = 16; o > 0; o >>= 1) v += __shfl_xor_sync(0xffffffffu, v, o);
    if ((tid & 31) == 0) sb[tid >> 5] = v;
    __syncthreads();
    if (tid == 0) {
        float s = 0.f;
        int nw = (blockDim.x + 31) >> 5;
        for (int i = 0; i < nw; i++) s += sb[i];
        sb[32] = s;
    }
    __syncthreads();
    return sb[32];
}

// ---------------- fp32 SGEMM: 128x128 tile, 8x8 micro, double-buffered ----------------
__global__ __launch_bounds__(256, 2)
void gemm128(const float* __restrict__ A, const float* __restrict__ B,
             float* __restrict__ C,
             int M, int N, int Kd, int lda, int ldb, int ldc,
             const int* __restrict__ rowmap,
             const float* __restrict__ addsrc,
             float* __restrict__ Cdup,
             const int* __restrict__ segoff,
             long long strideB,
             const float* __restrict__ rowscale) {
    int row0 = 0, rowEnd = M;
    const float* Bp = B;
    if (segoff) {
        int e = blockIdx.z;
        row0 = segoff[e];
        rowEnd = segoff[e + 1];
        Bp = B + (long long)e * strideB;
    }
    int rbase = row0 + blockIdx.y * 128;
    if (rbase >= rowEnd) return;
    int cbase = blockIdx.x * 128;

    __shared__ float As[2][16][132];
    __shared__ float Bs[2][16][132];

    int tid = threadIdx.x;
    int tx = tid & 15, ty = tid >> 4;

    int am = tid & 127;
    int ak0 = (tid >> 7) * 8;
    int arow_g = rbase + am;
    const float* Arow = nullptr;
    if (arow_g < rowEnd) {
        int m = rowmap ? rowmap[arow_g] : arow_g;
        Arow = A + (long long)m * lda;
    }
    int br0 = tid >> 5;
    int bc4 = tid & 31;

    float acc[8][8];
#pragma unroll
    for (int i = 0; i < 8; i++)
#pragma unroll
        for (int j = 0; j < 8; j++) acc[i][j] = 0.f;

    float4 ra0, ra1, rb0, rb1;
    const float4 Z = make_float4(0.f, 0.f, 0.f, 0.f);

#define LOADG(K0)                                                                    \
    do {                                                                             \
        if (Arow) {                                                                  \
            ra0 = *(const float4*)(Arow + (K0) + ak0);                               \
            ra1 = *(const float4*)(Arow + (K0) + ak0 + 4);                           \
        } else { ra0 = Z; ra1 = Z; }                                                 \
        rb0 = *(const float4*)(Bp + (long long)((K0) + br0) * ldb + cbase + bc4 * 4);\
        rb1 = *(const float4*)(Bp + (long long)((K0) + br0 + 8) * ldb + cbase + bc4 * 4);\
    } while (0)

#define STOREB(BUF)                                                                  \
    do {                                                                             \
        As[BUF][ak0 + 0][am] = ra0.x; As[BUF][ak0 + 1][am] = ra0.y;                  \
        As[BUF][ak0 + 2][am] = ra0.z; As[BUF][ak0 + 3][am] = ra0.w;                  \
        As[BUF][ak0 + 4][am] = ra1.x; As[BUF][ak0 + 5][am] = ra1.y;                  \
        As[BUF][ak0 + 6][am] = ra1.z; As[BUF][ak0 + 7][am] = ra1.w;                  \
        *(float4*)&Bs[BUF][br0][bc4 * 4] = rb0;                                      \
        *(float4*)&Bs[BUF][br0 + 8][bc4 * 4] = rb1;                                  \
    } while (0)

    int nk = Kd >> 4;
    LOADG(0);
    STOREB(0);
    __syncthreads();
    for (int kt = 0; kt < nk; kt++) {
        int cur = kt & 1;
        if (kt + 1 < nk) LOADG((kt + 1) * 16);
#pragma unroll
        for (int kk = 0; kk < 16; kk++) {
            float a[8], b[8];
            float4 t;
            t = *(const float4*)&As[cur][kk][ty * 8];     a[0] = t.x; a[1] = t.y; a[2] = t.z; a[3] = t.w;
            t = *(const float4*)&As[cur][kk][ty * 8 + 4]; a[4] = t.x; a[5] = t.y; a[6] = t.z; a[7] = t.w;
            t = *(const float4*)&Bs[cur][kk][tx * 8];     b[0] = t.x; b[1] = t.y; b[2] = t.z; b[3] = t.w;
            t = *(const float4*)&Bs[cur][kk][tx * 8 + 4]; b[4] = t.x; b[5] = t.y; b[6] = t.z; b[7] = t.w;
#pragma unroll
            for (int i = 0; i < 8; i++)
#pragma unroll
                for (int j = 0; j < 8; j++) acc[i][j] += a[i] * b[j];
        }
        if (kt + 1 < nk) {
            STOREB(cur ^ 1);
            __syncthreads();
        }
    }
#undef LOADG
#undef STOREB

#pragma unroll
    for (int i = 0; i < 8; i++) {
        int r = rbase + ty * 8 + i;
        if (r >= rowEnd) break;
        float sc = rowscale ? rowscale[r] : 1.f;
        long long base = (long long)r * ldc + cbase + tx * 8;
        float4 v0 = make_float4(acc[i][0] * sc, acc[i][1] * sc, acc[i][2] * sc, acc[i][3] * sc);
        float4 v1 = make_float4(acc[i][4] * sc, acc[i][5] * sc, acc[i][6] * sc, acc[i][7] * sc);
        if (addsrc) {
            float4 s0 = *(const float4*)(addsrc + base);
            float4 s1 = *(const float4*)(addsrc + base + 4);
            v0.x += s0.x; v0.y += s0.y; v0.z += s0.z; v0.w += s0.w;
            v1.x += s1.x; v1.y += s1.y; v1.z += s1.z; v1.w += s1.w;
        }
        *(float4*)(C + base) = v0;
        *(float4*)(C + base + 4) = v1;
        if (Cdup) {
            *(float4*)(Cdup + base) = v0;
            *(float4*)(Cdup + base + 4) = v1;
        }
    }
}

// ---------------- fused QKV GEMM: C = g_qkv[T][3072] ----------------
__global__ __launch_bounds__(256, 2)
void gemm128_qkv(const float* __restrict__ A,
                 const float* __restrict__ wq, const float* __restrict__ wk,
                 const float* __restrict__ wv) {
    int x = blockIdx.x;
    const float* Bp;
    int ldb, bcol;
    if (x < 16)      { Bp = wq; ldb = 2048; bcol = x * 128; }
    else if (x < 20) { Bp = wk; ldb = 512;  bcol = (x - 16) * 128; }
    else             { Bp = wv; ldb = 512;  bcol = (x - 20) * 128; }
    int ccol = x * 128;
    int rbase = blockIdx.y * 128;

    __shared__ float As[2][16][132];
    __shared__ float Bs[2][16][132];

    int tid = threadIdx.x;
    int tx = tid & 15, ty = tid >> 4;
    int am = tid & 127;
    int ak0 = (tid >> 7) * 8;
    const float* Arow = A + (long long)(rbase + am) * H_;
    int br0 = tid >> 5;
    int bc4 = tid & 31;

    float acc[8][8];
#pragma unroll
    for (int i = 0; i < 8; i++)
#pragma unroll
        for (int j = 0; j < 8; j++) acc[i][j] = 0.f;

    float4 ra0, ra1, rb0, rb1;
#define LOADG(K0)                                                                    \
    do {                                                                             \
        ra0 = *(const float4*)(Arow + (K0) + ak0);                                   \
        ra1 = *(const float4*)(Arow + (K0) + ak0 + 4);                               \
        rb0 = *(const float4*)(Bp + (long long)((K0) + br0) * ldb + bcol + bc4 * 4); \
        rb1 = *(const float4*)(Bp + (long long)((K0) + br0 + 8) * ldb + bcol + bc4 * 4);\
    } while (0)
#define STOREB(BUF)                                                                  \
    do {                                                                             \
        As[BUF][ak0 + 0][am] = ra0.x; As[BUF][ak0 + 1][am] = ra0.y;                  \
        As[BUF][ak0 + 2][am] = ra0.z; As[BUF][ak0 + 3][am] = ra0.w;                  \
        As[BUF][ak0 + 4][am] = ra1.x; As[BUF][ak0 + 5][am] = ra1.y;                  \
        As[BUF][ak0 + 6][am] = ra1.z; As[BUF][ak0 + 7][am] = ra1.w;                  \
        *(float4*)&Bs[BUF][br0][bc4 * 4] = rb0;                                      \
        *(float4*)&Bs[BUF][br0 + 8][bc4 * 4] = rb1;                                  \
    } while (0)

    int nk = H_ >> 4;
    LOADG(0);
    STOREB(0);
    __syncthreads();
    for (int kt = 0; kt < nk; kt++) {
        int cur = kt & 1;
        if (kt + 1 < nk) LOADG((kt + 1) * 16);
#pragma unroll
        for (int kk = 0; kk < 16; kk++) {
            float a[8], b[8];
            float4 t;
            t = *(const float4*)&As[cur][kk][ty * 8];     a[0] = t.x; a[1] = t.y; a[2] = t.z; a[3] = t.w;
            t = *(const float4*)&As[cur][kk][ty * 8 + 4]; a[4] = t.x; a[5] = t.y; a[6] = t.z; a[7] = t.w;
            t = *(const float4*)&Bs[cur][kk][tx * 8];     b[0] = t.x; b[1] = t.y; b[2] = t.z; b[3] = t.w;
            t = *(const float4*)&Bs[cur][kk][tx * 8 + 4]; b[4] = t.x; b[5] = t.y; b[6] = t.z; b[7] = t.w;
#pragma unroll
            for (int i = 0; i < 8; i++)
#pragma unroll
                for (int j = 0; j < 8; j++) acc[i][j] += a[i] * b[j];
        }
        if (kt + 1 < nk) {
            STOREB(cur ^ 1);
            __syncthreads();
        }
    }
#undef LOADG
#undef STOREB
#pragma unroll
    for (int i = 0; i < 8; i++) {
        int r = rbase + ty * 8 + i;
        long long base = (long long)r * 3072 + ccol + tx * 8;
        *(float4*)(g_qkv + base) = make_float4(acc[i][0], acc[i][1], acc[i][2], acc[i][3]);
        *(float4*)(g_qkv + base + 4) = make_float4(acc[i][4], acc[i][5], acc[i][6], acc[i][7]);
    }
}

// ---------------- embed lookup + rms -> concat ----------------
__global__ void embcat_kernel(const int* __restrict__ ids,
                              const float* __restrict__ emb_w,
                              const float* __restrict__ hid,
                              const float* __restrict__ we,
                              const float* __restrict__ wh) {
    int t = blockIdx.x;
    const float* er = emb_w + (size_t)ids[t] * H_;
    const float* hr = hid + (size_t)t * H_;
    float ss = 0.f;
    for (int h = threadIdx.x; h < H_; h += blockDim.x) { float v = er[h]; ss += v * v; }
    float tot = block_reduce_sum(ss);
    float rs = rsqrtf(tot / H_ + EPS_);
    for (int h = threadIdx.x; h < H_; h += blockDim.x)
        g_cat[(size_t)t * 2 * H_ + h] = er[h] * rs * (1.f + we[h]);
    ss = 0.f;
    for (int h = threadIdx.x; h < H_; h += blockDim.x) { float v = hr[h]; ss += v * v; }
    tot = block_reduce_sum(ss);
    rs = rsqrtf(tot / H_ + EPS_);
    for (int h = threadIdx.x; h < H_; h += blockDim.x)
        g_cat[(size_t)t * 2 * H_ + H_ + h] = hr[h] * rs * (1.f + wh[h]);
}

// ---------------- row RMS norm ----------------
__global__ void rmsnorm_kernel(const float* __restrict__ in,
                               const float* __restrict__ w,
                               float* __restrict__ out) {
    int t = blockIdx.x;
    const float* r = in + (size_t)t * H_;
    float ss = 0.f;
    for (int h = threadIdx.x; h < H_; h += blockDim.x) { float v = r[h]; ss += v * v; }
    float tot = block_reduce_sum(ss);
    float rs = rsqrtf(tot / H_ + EPS_);
    for (int h = threadIdx.x; h < H_; h += blockDim.x)
        out[(size_t)t * H_ + h] = r[h] * rs * (1.f + w[h]);
}

// ---------------- per-head rms + rope (in place on g_qkv) ----------------
__global__ void qkrope_kernel(int coloff, int nheads,
                              const float* __restrict__ nw,
                              const int* __restrict__ positions) {
    int t = blockIdx.x, h = blockIdx.y;
    float* v = g_qkv + (size_t)t * 3072 + coloff + h * DH_;
    int d = threadIdx.x;
    float val = v[d];
    float ss = val * val;
#pragma unroll
    for (int o = 16; o > 0; o >>= 1) ss += __shfl_xor_sync(0xffffffffu, ss, o);
    __shared__ float ws[4];
    if ((d & 31) == 0) ws[d >> 5] = ss;
    __syncthreads();
    float tot = ws[0] + ws[1] + ws[2] + ws[3];
    float rs = rsqrtf(tot / DH_ + EPS_);
    float n = val * rs * (1.f + nw[d]);
    __shared__ float nv[DH_];
    nv[d] = n;
    __syncthreads();
    int pos = positions[t];
    int i = d & 63;
    float inv = expf(-((float)i / 64.f) * 13.815510557964274f);
    float ang = (float)pos * inv;
    float c = cosf(ang), s = sinf(ang);
    float outv;
    if (d < 64) outv = nv[d] * c - nv[d + 64] * s;
    else        outv = nv[d] * c + nv[d - 64] * s;
    v[d] = outv;
}

// ---------------- attention v3: gemm-shaped, 64x64 tiles ----------------
#define ATP 68
#define AVP 132
#define ATT3_SMEM ((2 * 128 * ATP + 64 * ATP + 64 * AVP + 128 + 128) * 4)
__global__ __launch_bounds__(256)
void attn3_kernel(const int* __restrict__ positions) {
    int qt = blockIdx.x, h = blockIdx.y;
    int qbase = qt * 64;
    int kvh = h >> 2;
    extern __shared__ float sm3[];
    float* QT = sm3;                    // [128][ATP]
    float* KT = QT + 128 * ATP;         // [128][ATP]
    float* PT = KT + 128 * ATP;         // [64][ATP]
    float* Vs = PT + 64 * ATP;          // [64][AVP]
    float* mrow = Vs + 64 * AVP;        // [64]
    float* lrow = mrow + 64;            // [64]
    int* qpos = (int*)(lrow + 64);      // [64]
    int* kpos = qpos + 64;              // [64]

    int tid = threadIdx.x;
    int tx = tid & 15, ty = tid >> 4;
    int r = tid & 63;
    int dc = (tid >> 6) * 32;

    // stage Q^T once
    {
        const float* qsrc = g_qkv + (size_t)(qbase + r) * 3072 + h * DH_;
#pragma unroll
        for (int i2 = 0; i2 < 8; i2++) {
            int d = dc + i2 * 4;
            float4 v = *(const float4*)(qsrc + d);
            QT[(d + 0) * ATP + r] = v.x;
            QT[(d + 1) * ATP + r] = v.y;
            QT[(d + 2) * ATP + r] = v.z;
            QT[(d + 3) * ATP + r] = v.w;
        }
        if (tid < 64) {
            qpos[tid] = positions[qbase + tid];
            mrow[tid] = -1e30f;
            lrow[tid] = 0.f;
        }
    }
    float acc[4][8];
#pragma unroll
    for (int i = 0; i < 4; i++)
#pragma unroll
        for (int n = 0; n < 8; n++) acc[i][n] = 0.f;
    const float scale = 0.08838834764831845f;

    for (int kt = 0; kt <= qt; kt++) {
        int kbase = kt * 64;
        __syncthreads();
        // stage K^T and V
        {
            const float* ksrc = g_qkv + (size_t)(kbase + r) * 3072 + 2048 + kvh * DH_;
            const float* vsrc = g_qkv + (size_t)(kbase + r) * 3072 + 2560 + kvh * DH_;
#pragma unroll
            for (int i2 = 0; i2 < 8; i2++) {
                int d = dc + i2 * 4;
                float4 kv = *(const float4*)(ksrc + d);
                KT[(d + 0) * ATP + r] = kv.x;
                KT[(d + 1) * ATP + r] = kv.y;
                KT[(d + 2) * ATP + r] = kv.z;
                KT[(d + 3) * ATP + r] = kv.w;
                *(float4*)&Vs[r * AVP + d] = *(const float4*)(vsrc + d);
            }
            if (tid < 64) kpos[tid] = positions[kbase + tid];
        }
        __syncthreads();

        // scores: 4x4 per thread
        float s0[4][4];
#pragma unroll
        for (int i = 0; i < 4; i++)
#pragma unroll
            for (int j = 0; j < 4; j++) s0[i][j] = 0.f;
#pragma unroll 8
        for (int kk = 0; kk < 128; kk++) {
            float4 a = *(const float4*)&QT[kk * ATP + ty * 4];
            float4 b = *(const float4*)&KT[kk * ATP + tx * 4];
            s0[0][0] += a.x * b.x; s0[0][1] += a.x * b.y; s0[0][2] += a.x * b.z; s0[0][3] += a.x * b.w;
            s0[1][0] += a.y * b.x; s0[1][1] += a.y * b.y; s0[1][2] += a.y * b.z; s0[1][3] += a.y * b.w;
            s0[2][0] += a.z * b.x; s0[2][1] += a.z * b.y; s0[2][2] += a.z * b.z; s0[2][3] += a.z * b.w;
            s0[3][0] += a.w * b.x; s0[3][1] += a.w * b.y; s0[3][2] += a.w * b.z; s0[3][3] += a.w * b.w;
        }
        // mask + online softmax (rows owned by fixed half-warps)
        int kp0 = kpos[tx * 4 + 0], kp1 = kpos[tx * 4 + 1];
        int kp2 = kpos[tx * 4 + 2], kp3 = kpos[tx * 4 + 3];
#pragma unroll
        for (int i = 0; i < 4; i++) {
            int row = ty * 4 + i;
            int qp = qpos[row];
            s0[i][0] = (kp0 <= qp) ? s0[i][0] * scale : -1e30f;
            s0[i][1] = (kp1 <= qp) ? s0[i][1] * scale : -1e30f;
            s0[i][2] = (kp2 <= qp) ? s0[i][2] * scale : -1e30f;
            s0[i][3] = (kp3 <= qp) ? s0[i][3] * scale : -1e30f;
            float mx = fmaxf(fmaxf(s0[i][0], s0[i][1]), fmaxf(s0[i][2], s0[i][3]));
            mx = fmaxf(mx, __shfl_xor_sync(0xffffffffu, mx, 1));
            mx = fmaxf(mx, __shfl_xor_sync(0xffffffffu, mx, 2));
            mx = fmaxf(mx, __shfl_xor_sync(0xffffffffu, mx, 4));
            mx = fmaxf(mx, __shfl_xor_sync(0xffffffffu, mx, 8));
            float mold = mrow[row];
            float mnew = fmaxf(mold, mx);
            float al = __expf(mold - mnew);
            float rs = 0.f;
#pragma unroll
            for (int j = 0; j < 4; j++) {
                float p = __expf(s0[i][j] - mnew);
                s0[i][j] = p;
                rs += p;
            }
            rs += __shfl_xor_sync(0xffffffffu, rs, 1);
            rs += __shfl_xor_sync(0xffffffffu, rs, 2);
            rs += __shfl_xor_sync(0xffffffffu, rs, 4);
            rs += __shfl_xor_sync(0xffffffffu, rs, 8);
            if (tx == 0) {
                mrow[row] = mnew;
                lrow[row] = lrow[row] * al + rs;
            }
#pragma unroll
            for (int n = 0; n < 8; n++) acc[i][n] *= al;
        }
        // store P transposed (vector over the 4 q-rows)
#pragma unroll
        for (int j = 0; j < 4; j++) {
            *(float4*)&PT[(tx * 4 + j) * ATP + ty * 4] =
                make_float4(s0[0][j], s0[1][j], s0[2][j], s0[3][j]);
        }
        __syncthreads();
        // PV: 4x8 per thread
#pragma unroll 2
        for (int kr = 0; kr < 64; kr++) {
            float4 a = *(const float4*)&PT[kr * ATP + ty * 4];
            float4 b0 = *(const float4*)&Vs[kr * AVP + tx * 8];
            float4 b1 = *(const float4*)&Vs[kr * AVP + tx * 8 + 4];
            acc[0][0] += a.x * b0.x; acc[0][1] += a.x * b0.y; acc[0][2] += a.x * b0.z; acc[0][3] += a.x * b0.w;
            acc[0][4] += a.x * b1.x; acc[0][5] += a.x * b1.y; acc[0][6] += a.x * b1.z; acc[0][7] += a.x * b1.w;
            acc[1][0] += a.y * b0.x; acc[1][1] += a.y * b0.y; acc[1][2] += a.y * b0.z; acc[1][3] += a.y * b0.w;
            acc[1][4] += a.y * b1.x; acc[1][5] += a.y * b1.y; acc[1][6] += a.y * b1.z; acc[1][7] += a.y * b1.w;
            acc[2][0] += a.z * b0.x; acc[2][1] += a.z * b0.y; acc[2][2] += a.z * b0.z; acc[2][3] += a.z * b0.w;
            acc[2][4] += a.z * b1.x; acc[2][5] += a.z * b1.y; acc[2][6] += a.z * b1.z; acc[2][7] += a.z * b1.w;
            acc[3][0] += a.w * b0.x; acc[3][1] += a.w * b0.y; acc[3][2] += a.w * b0.z; acc[3][3] += a.w * b0.w;
            acc[3][4] += a.w * b1.x; acc[3][5] += a.w * b1.y; acc[3][6] += a.w * b1.z; acc[3][7] += a.w * b1.w;
        }
    }
    // epilogue
#pragma unroll
    for (int i = 0; i < 4; i++) {
        int row = ty * 4 + i;
        int qrow = qbase + row;
        float inv = 1.f / lrow[row];
        float* dst = g_attn + (size_t)qrow * (NH_ * DH_) + h * DH_ + tx * 8;
        *(float4*)dst = make_float4(acc[i][0] * inv, acc[i][1] * inv,
                                    acc[i][2] * inv, acc[i][3] * inv);
        *(float4*)(dst + 4) = make_float4(acc[i][4] * inv, acc[i][5] * inv,
                                          acc[i][6] * inv, acc[i][7] * inv);
    }
}

// ---------------- router ----------------
__global__ void zero_counts_kernel() {
    if (threadIdx.x < E_) g_counts[threadIdx.x] = 0;
}

__global__ void router_kernel(const float* __restrict__ rw) {
    int t = blockIdx.x;
    __shared__ float part[256];
    __shared__ float logits[E_];
    int tid = threadIdx.x;
    int e = tid >> 4, c = tid & 15;
    float s = 0.f;
    const float* xr = g_xn + (size_t)t * H_;
    for (int h = c * 128; h < (c + 1) * 128; h++) s += xr[h] * rw[(size_t)h * E_ + e];
    part[tid] = s;
    __syncthreads();
    if (c == 0) {
        float tot = 0.f;
        for (int i = 0; i < 16; i++) tot += part[e * 16 + i];
        logits[e] = tot;
    }
    __syncthreads();
    if (tid == 0) {
        float mx = -1e30f;
        for (int i = 0; i < E_; i++) mx = fmaxf(mx, logits[i]);
        float p[E_];
        for (int i = 0; i < E_; i++) p[i] = expf(logits[i] - mx);
        int i0 = 0; float v0 = p[0];
        for (int i = 1; i < E_; i++) if (p[i] > v0) { v0 = p[i]; i0 = i; }
        int i1 = -1; float v1 = -1.f;
        for (int i = 0; i < E_; i++) if (i != i0 && p[i] > v1) { v1 = p[i]; i1 = i; }
        float denom = v0 + v1;
        g_top_idx[t * 2 + 0] = i0;
        g_top_idx[t * 2 + 1] = i1;
        g_top_w[t * 2 + 0] = v0 / denom;
        g_top_w[t * 2 + 1] = v1 / denom;
        atomicAdd(&g_counts[i0], 1);
        atomicAdd(&g_counts[i1], 1);
    }
}

__global__ void offsets_kernel() {
    if (threadIdx.x == 0) {
        int acc = 0;
        for (int e = 0; e < E_; e++) { g_offs[e] = acc; acc += g_counts[e]; }
        g_offs[E_] = acc;
    }
    if (threadIdx.x < E_) g_counts2[threadIdx.x] = 0;
}

__global__ void scatter_kernel() {
    int t = blockIdx.x * blockDim.x + threadIdx.x;
    if (t >= T_) return;
    for (int k = 0; k < TOPK_; k++) {
        int e = g_top_idx[t * 2 + k];
        int pos = atomicAdd(&g_counts2[e], 1);
        int slot = g_offs[e] + pos;
        g_tok_of_slot[slot] = t;
        g_gate_of_slot[slot] = g_top_w[t * 2 + k];
        g_slot_of_tok[t * 2 + k] = slot;
    }
}

// ---------------- silu(g)*u in place ----------------
__global__ void silu_mul_kernel() {
    size_t i = (size_t)blockIdx.x * blockDim.x + threadIdx.x;
    if (i >= (size_t)T_ * TOPK_ * I_) return;
    float x = g_gbuf[i];
    g_gbuf[i] = (x / (1.f + expf(-x))) * g_ubuf[i];
}

// ---------------- final combine + rms ----------------
__global__ void final_kernel(const float* __restrict__ fw, float* __restrict__ out) {
    int t = blockIdx.x;
    __shared__ float buf[H_];
    int s0 = g_slot_of_tok[t * 2 + 0];
    int s1 = g_slot_of_tok[t * 2 + 1];
    float ss = 0.f;
    for (int h = threadIdx.x; h < H_; h += blockDim.x) {
        float v = g_x[(size_t)t * H_ + h] + g_downbuf[(size_t)s0 * H_ + h] +
                  g_downbuf[(size_t)s1 * H_ + h];
        buf[h] = v;
        ss += v * v;
    }
    float tot = block_reduce_sum(ss);
    float rs = rsqrtf(tot / H_ + EPS_);
    for (int h = threadIdx.x; h < H_; h += blockDim.x)
        out[(size_t)t * H_ + h] = buf[h] * rs * (1.f + fw[h]);
}

// ---------------- launch ----------------
extern "C" void kernel_launch(void* const* d_in, const int* in_sizes, int n_in,
                              void* d_out, int out_size) {
    const int* input_ids      = (const int*)d_in[0];
    const int* positions      = (const int*)d_in[1];
    const float* hidden       = (const float*)d_in[2];
    const float* embed_w      = (const float*)d_in[4];
    const float* fc_w         = (const float*)d_in[5];
    const float* pre_fc_emb_w = (const float*)d_in[6];
    const float* pre_fc_hid_w = (const float*)d_in[7];
    const float* in_ln_w      = (const float*)d_in[8];
    const float* post_ln_w    = (const float*)d_in[9];
    const float* final_norm_w = (const float*)d_in[10];
    const float* wq           = (const float*)d_in[11];
    const float* wk           = (const float*)d_in[12];
    const float* wv           = (const float*)d_in[13];
    const float* wo           = (const float*)d_in[14];
    const float* q_norm_w     = (const float*)d_in[15];
    const float* k_norm_w     = (const float*)d_in[16];
    const float* router_w     = (const float*)d_in[17];
    const float* w_gate       = (const float*)d_in[18];
    const float* w_up         = (const float*)d_in[19];
    const float* w_down       = (const float*)d_in[20];
    float* out = (float*)d_out;

    float *p_cat, *p_x, *p_res, *p_xn, *p_attn, *p_g, *p_u, *p_down, *p_gate;
    int *p_tok, *p_offs;
    cudaGetSymbolAddress((void**)&p_cat, g_cat);
    cudaGetSymbolAddress((void**)&p_x, g_x);
    cudaGetSymbolAddress((void**)&p_res, g_res);
    cudaGetSymbolAddress((void**)&p_xn, g_xn);
    cudaGetSymbolAddress((void**)&p_attn, g_attn);
    cudaGetSymbolAddress((void**)&p_g, g_gbuf);
    cudaGetSymbolAddress((void**)&p_u, g_ubuf);
    cudaGetSymbolAddress((void**)&p_down, g_downbuf);
    cudaGetSymbolAddress((void**)&p_gate, g_gate_of_slot);
    cudaGetSymbolAddress((void**)&p_tok, g_tok_of_slot);
    cudaGetSymbolAddress((void**)&p_offs, g_offs);

    cudaFuncSetAttribute(attn3_kernel, cudaFuncAttributeMaxDynamicSharedMemorySize,
                         ATT3_SMEM);

    // 1. embed + rms -> concat
    embcat_kernel<<<T_, 256>>>(input_ids, embed_w, hidden, pre_fc_emb_w, pre_fc_hid_w);

    // 2. fc: x = cat @ fc_w ; residual = x
    gemm128<<<dim3(H_ / 128, T_ / 128), 256>>>(p_cat, fc_w, p_x, T_, H_, 2 * H_,
                                               2 * H_, H_, H_, nullptr, nullptr, p_res,
                                               nullptr, 0, nullptr);

    // 3. in_ln
    rmsnorm_kernel<<<T_, 256>>>(p_x, in_ln_w, p_xn);

    // 4. fused qkv -> g_qkv
    gemm128_qkv<<<dim3(24, T_ / 128), 256>>>(p_xn, wq, wk, wv);

    // 5. q/k norm + rope (in place on g_qkv)
    qkrope_kernel<<<dim3(T_, NH_), DH_>>>(0, NH_, q_norm_w, positions);
    qkrope_kernel<<<dim3(T_, NKV_), DH_>>>(2048, NKV_, k_norm_w, positions);

    // 6. attention
    attn3_kernel<<<dim3(T_ / 64, NH_), 256, ATT3_SMEM>>>(positions);

    // 7. wo + residual -> x
    gemm128<<<dim3(H_ / 128, T_ / 128), 256>>>(p_attn, wo, p_x, T_, H_, NH_ * DH_,
                                               NH_ * DH_, H_, H_, nullptr, p_res, nullptr,
                                               nullptr, 0, nullptr);

    // 8. post_ln
    rmsnorm_kernel<<<T_, 256>>>(p_x, post_ln_w, p_xn);

    // 9. router + bucketing
    zero_counts_kernel<<<1, 32>>>();
    router_kernel<<<T_, 256>>>(router_w);
    offsets_kernel<<<1, 32>>>();
    scatter_kernel<<<(T_ + 255) / 256, 256>>>();

    // 10. MoE grouped GEMMs
    gemm128<<<dim3(I_ / 128, T_ / 128, E_), 256>>>(p_xn, w_gate, p_g, 0, I_, H_,
                                                   H_, I_, I_, p_tok, nullptr, nullptr,
                                                   p_offs, (long long)H_ * I_, nullptr);
    gemm128<<<dim3(I_ / 128, T_ / 128, E_), 256>>>(p_xn, w_up, p_u, 0, I_, H_,
                                                   H_, I_, I_, p_tok, nullptr, nullptr,
                                                   p_offs, (long long)H_ * I_, nullptr);
    silu_mul_kernel<<<((size_t)T_ * TOPK_ * I_ + 255) / 256, 256>>>();
    gemm128<<<dim3(H_ / 128, T_ / 128, E_), 256>>>(p_g, w_down, p_down, 0, H_, I_,
                                                   I_, H_, H_, nullptr, nullptr, nullptr,
                                                   p_offs, (long long)I_ * H_, p_gate);

    // 11. combine + final rms
    final_kernel<<<T_, 256>>>(final_norm_w, out);
}